// round 1
// baseline (speedup 1.0000x reference)
#include <cuda_runtime.h>
#include <math.h>

#define BB   64
#define TT   256
#define EE   256
#define HH   1024
#define H3   3072
#define VOCAB 10000

// Scratch: input projections xw[dir][t][b][j] (includes input bias), ~402MB
__device__ float g_xw[(size_t)2 * TT * BB * H3];
// Hidden state ping-pong: [dir][parity][b][j]
__device__ float g_h[2][2][BB][HH];

// ---------------------------------------------------------------------------
// Init hidden state for both directions
// ---------------------------------------------------------------------------
__global__ __launch_bounds__(256) void init_h_kernel(const float* __restrict__ hidden) {
    int i = blockIdx.x * blockDim.x + threadIdx.x;   // 0 .. 2*B*H-1
    int dir = i / (BB * HH);
    int r   = i % (BB * HH);
    g_h[dir][0][r / HH][r % HH] = hidden[r];
}

// ---------------------------------------------------------------------------
// Fused embedding + input projection GEMM:
//   xw[dir][t][b][j] = sum_e emb[x[b][t]][e] * W[e][j] + bi[j]
// M = T*B (row m = t*64+b), N = 3072, K = 256. Tile 64x64, K-chunk 32.
// ---------------------------------------------------------------------------
__global__ __launch_bounds__(256) void input_proj_kernel(
    const int* __restrict__ x, const float* __restrict__ emb,
    const float* __restrict__ Wf, const float* __restrict__ bf,
    const float* __restrict__ Wb, const float* __restrict__ bb)
{
    const int dir = blockIdx.z;
    const float* __restrict__ W  = dir ? Wb : Wf;
    const float* __restrict__ bi = dir ? bb : bf;   // row 0 of b = input bias

    const int m0 = blockIdx.y * 64;
    const int n0 = blockIdx.x * 64;

    __shared__ float sA[64][32];   // [m][k]
    __shared__ float sB[32][64];   // [k][n]
    __shared__ int   sRow[64];

    const int tid = threadIdx.x;
    if (tid < 64) {
        int m = m0 + tid;
        int t = m >> 6;
        int b = m & 63;
        sRow[tid] = x[b * TT + t];
    }
    __syncthreads();

    const int ty = tid >> 4;       // 0..15
    const int tx = tid & 15;       // 0..15
    float acc[4][4] = {};

    for (int k0 = 0; k0 < EE; k0 += 32) {
        // Load A tile (gathered embedding rows): 64x32 floats, 2 float4/thread
        #pragma unroll
        for (int r = 0; r < 2; r++) {
            int f  = tid + r * 256;        // 0..511
            int m  = f >> 3;               // 0..63
            int kc = (f & 7) * 4;          // 0..28
            float4 v = *(const float4*)&emb[(size_t)sRow[m] * EE + k0 + kc];
            *(float4*)&sA[m][kc] = v;
        }
        // Load B tile: 32x64 floats
        #pragma unroll
        for (int r = 0; r < 2; r++) {
            int f  = tid + r * 256;
            int kk = f >> 4;               // 0..31
            int nc = (f & 15) * 4;         // 0..60
            float4 v = *(const float4*)&W[(size_t)(k0 + kk) * H3 + n0 + nc];
            *(float4*)&sB[kk][nc] = v;
        }
        __syncthreads();

        #pragma unroll
        for (int k = 0; k < 32; k++) {
            float4 bv = *(float4*)&sB[k][tx * 4];
            float a0 = sA[ty * 4 + 0][k];
            float a1 = sA[ty * 4 + 1][k];
            float a2 = sA[ty * 4 + 2][k];
            float a3 = sA[ty * 4 + 3][k];
            acc[0][0] += a0 * bv.x; acc[0][1] += a0 * bv.y; acc[0][2] += a0 * bv.z; acc[0][3] += a0 * bv.w;
            acc[1][0] += a1 * bv.x; acc[1][1] += a1 * bv.y; acc[1][2] += a1 * bv.z; acc[1][3] += a1 * bv.w;
            acc[2][0] += a2 * bv.x; acc[2][1] += a2 * bv.y; acc[2][2] += a2 * bv.z; acc[2][3] += a2 * bv.w;
            acc[3][0] += a3 * bv.x; acc[3][1] += a3 * bv.y; acc[3][2] += a3 * bv.z; acc[3][3] += a3 * bv.w;
        }
        __syncthreads();
    }

    float* xw = g_xw + ((size_t)dir * TT * BB + m0) * H3;
    #pragma unroll
    for (int i = 0; i < 4; i++) {
        int m = ty * 4 + i;
        int n = n0 + tx * 4;
        float4 o;
        o.x = acc[i][0] + bi[n + 0];
        o.y = acc[i][1] + bi[n + 1];
        o.z = acc[i][2] + bi[n + 2];
        o.w = acc[i][3] + bi[n + 3];
        *(float4*)&xw[(size_t)m * H3 + n] = o;
    }
}

// ---------------------------------------------------------------------------
// One GRU timestep, both directions (blockIdx.y = dir).
// CTA: 64 batch rows x 16 hidden columns. Thread: 4 batch x 1 column,
// computes 3 dot products (z, r, h gates) over K=H=1024, h chunks in SMEM.
// ---------------------------------------------------------------------------
__global__ __launch_bounds__(256) void gru_step_kernel(
    int s,
    const float* __restrict__ Uf, const float* __restrict__ bf,
    const float* __restrict__ Ub, const float* __restrict__ bb,
    float* __restrict__ out)
{
    const int dir = blockIdx.y;
    const int p   = s & 1;
    const float* __restrict__ U  = dir ? Ub : Uf;
    const float* __restrict__ br = (dir ? bb : bf) + H3;   // row 1 = recurrent bias
    const int tt = dir ? (TT - 1 - s) : s;                 // time index into xw & output

    const float* __restrict__ xw = g_xw + ((size_t)dir * TT * BB + (size_t)tt * BB) * H3;
    const float* __restrict__ hp = &g_h[dir][p][0][0];
    float* __restrict__ hn       = &g_h[dir][p ^ 1][0][0];

    const int tid = threadIdx.x;     // 256
    const int jl  = tid & 15;
    const int bq  = tid >> 4;        // 0..15
    const int j   = blockIdx.x * 16 + jl;
    const int b0  = bq * 4;

    __shared__ float sH[64][64];     // [k][b], one K-chunk of h

    float az[4] = {0.f, 0.f, 0.f, 0.f};
    float ar[4] = {0.f, 0.f, 0.f, 0.f};
    float ah[4] = {0.f, 0.f, 0.f, 0.f};

    for (int k0 = 0; k0 < HH; k0 += 64) {
        // Cooperative load of h chunk, transposed to [k][b]
        {
            int b  = tid & 63;
            int kc = (tid >> 6) * 16;
            const float* src = hp + (size_t)b * HH + k0 + kc;
            #pragma unroll
            for (int q = 0; q < 4; q++) {
                float4 v = *(const float4*)(src + q * 4);
                sH[kc + q * 4 + 0][b] = v.x;
                sH[kc + q * 4 + 1][b] = v.y;
                sH[kc + q * 4 + 2][b] = v.z;
                sH[kc + q * 4 + 3][b] = v.w;
            }
        }
        __syncthreads();

        const float* Urow = U + (size_t)k0 * H3;
        #pragma unroll 8
        for (int k = 0; k < 64; k++) {
            size_t off = (size_t)k * H3 + j;
            float uz = Urow[off];
            float ur = Urow[off + HH];
            float uh = Urow[off + 2 * HH];
            float4 h4 = *(const float4*)&sH[k][b0];
            az[0] += h4.x * uz; ar[0] += h4.x * ur; ah[0] += h4.x * uh;
            az[1] += h4.y * uz; ar[1] += h4.y * ur; ah[1] += h4.y * uh;
            az[2] += h4.z * uz; ar[2] += h4.z * ur; ah[2] += h4.z * uh;
            az[3] += h4.w * uz; ar[3] += h4.w * ur; ah[3] += h4.w * uh;
        }
        __syncthreads();
    }

    const float brz = br[j];
    const float brr = br[HH + j];
    const float brh = br[2 * HH + j];

    #pragma unroll
    for (int i = 0; i < 4; i++) {
        int b = b0 + i;
        const float* xwb = xw + (size_t)b * H3;
        float xz = xwb[j];
        float xr = xwb[HH + j];
        float xh = xwb[2 * HH + j];
        float hz = az[i] + brz;
        float hr = ar[i] + brr;
        float hh = ah[i] + brh;
        float z  = 1.f / (1.f + __expf(-(xz + hz)));
        float r  = 1.f / (1.f + __expf(-(xr + hr)));
        float cand = tanhf(xh + r * hh);
        float hprev = hp[(size_t)b * HH + j];
        float v = z * hprev + (1.f - z) * cand;
        hn[(size_t)b * HH + j] = v;
        out[((size_t)b * TT + tt) * (2 * HH) + dir * HH + j] = v;
    }
}

// ---------------------------------------------------------------------------
// Write final hidden states hf, hb after the output tensor.
// After 256 steps (last step s=255 has parity 1, writes parity 0), final h
// sits in parity slot 0.
// ---------------------------------------------------------------------------
__global__ __launch_bounds__(256) void finalize_kernel(float* __restrict__ out) {
    int i = blockIdx.x * blockDim.x + threadIdx.x;   // 0 .. 2*B*H-1
    int dir = i / (BB * HH);
    int r   = i % (BB * HH);
    float v = g_h[dir][0][r / HH][r % HH];
    out[(size_t)BB * TT * 2 * HH + (size_t)dir * BB * HH + r] = v;
}

// ---------------------------------------------------------------------------
// Launch. Inputs (metadata order): x, hidden, emb, Wf, Uf, bf, Wb, Ub, bb.
// Output: concat (B,T,2H) then hf (B,H) then hb (B,H), all float32.
// ---------------------------------------------------------------------------
extern "C" void kernel_launch(void* const* d_in, const int* in_sizes, int n_in,
                              void* d_out, int out_size)
{
    const int*   x      = (const int*)  d_in[0];
    const float* hidden = (const float*)d_in[1];
    const float* emb    = (const float*)d_in[2];
    const float* Wf     = (const float*)d_in[3];
    const float* Uf     = (const float*)d_in[4];
    const float* bf     = (const float*)d_in[5];
    const float* Wb     = (const float*)d_in[6];
    const float* Ub     = (const float*)d_in[7];
    const float* bb     = (const float*)d_in[8];
    float* out = (float*)d_out;

    // Init hidden states
    init_h_kernel<<<(2 * BB * HH) / 256, 256>>>(hidden);

    // Input projections for both directions
    {
        dim3 grid(H3 / 64, (TT * BB) / 64, 2);
        input_proj_kernel<<<grid, 256>>>(x, emb, Wf, bf, Wb, bb);
    }

    // Sequential scan: one launch per timestep, both directions inside
    {
        dim3 grid(HH / 16, 2);
        for (int s = 0; s < TT; s++) {
            gru_step_kernel<<<grid, 256>>>(s, Uf, bf, Ub, bb, out);
        }
    }

    // Final hidden states
    finalize_kernel<<<(2 * BB * HH) / 256, 256>>>(out);
}

// round 3
// speedup vs baseline: 3.9057x; 3.9057x over previous
#include <cuda_runtime.h>
#include <math.h>

#define BB   64
#define TT   256
#define EE   256
#define HH   1024
#define H3   3072

// Scratch: input projections xw[dir][t][b][j] (includes input bias), ~402MB
__device__ float g_xw[(size_t)2 * TT * BB * H3];
// Hidden state ping-pong: [dir][parity][b][j]
__device__ float g_h[2][2][BB][HH];
// Grid barrier counters, one per direction (monotonic within a launch)
__device__ unsigned int g_bar[2];

// ---------------------------------------------------------------------------
// Init hidden state for both directions + reset barrier counters
// ---------------------------------------------------------------------------
__global__ __launch_bounds__(256) void init_h_kernel(const float* __restrict__ hidden) {
    int i = blockIdx.x * blockDim.x + threadIdx.x;   // 0 .. 2*B*H-1
    if (i == 0) { g_bar[0] = 0u; g_bar[1] = 0u; }
    int dir = i / (BB * HH);
    int r   = i % (BB * HH);
    g_h[dir][0][r / HH][r % HH] = hidden[r];
}

// ---------------------------------------------------------------------------
// Fused embedding + input projection GEMM:
//   xw[dir][t][b][j] = sum_e emb[x[b][t]][e] * W[e][j] + bi[j]
// M = T*B (row m = t*64+b), N = 3072, K = 256. Tile 64x64, K-chunk 32.
// ---------------------------------------------------------------------------
__global__ __launch_bounds__(256) void input_proj_kernel(
    const int* __restrict__ x, const float* __restrict__ emb,
    const float* __restrict__ Wf, const float* __restrict__ bf,
    const float* __restrict__ Wb, const float* __restrict__ bb)
{
    const int dir = blockIdx.z;
    const float* __restrict__ W  = dir ? Wb : Wf;
    const float* __restrict__ bi = dir ? bb : bf;   // row 0 of b = input bias

    const int m0 = blockIdx.y * 64;
    const int n0 = blockIdx.x * 64;

    __shared__ float sA[64][32];   // [m][k]
    __shared__ float sB[32][64];   // [k][n]
    __shared__ int   sRow[64];

    const int tid = threadIdx.x;
    if (tid < 64) {
        int m = m0 + tid;
        int t = m >> 6;
        int b = m & 63;
        sRow[tid] = x[b * TT + t];
    }
    __syncthreads();

    const int ty = tid >> 4;       // 0..15
    const int tx = tid & 15;       // 0..15
    float acc[4][4] = {};

    for (int k0 = 0; k0 < EE; k0 += 32) {
        #pragma unroll
        for (int r = 0; r < 2; r++) {
            int f  = tid + r * 256;        // 0..511
            int m  = f >> 3;               // 0..63
            int kc = (f & 7) * 4;          // 0..28
            float4 v = *(const float4*)&emb[(size_t)sRow[m] * EE + k0 + kc];
            *(float4*)&sA[m][kc] = v;
        }
        #pragma unroll
        for (int r = 0; r < 2; r++) {
            int f  = tid + r * 256;
            int kk = f >> 4;               // 0..31
            int nc = (f & 15) * 4;         // 0..60
            float4 v = *(const float4*)&W[(size_t)(k0 + kk) * H3 + n0 + nc];
            *(float4*)&sB[kk][nc] = v;
        }
        __syncthreads();

        #pragma unroll
        for (int k = 0; k < 32; k++) {
            float4 bv = *(float4*)&sB[k][tx * 4];
            float a0 = sA[ty * 4 + 0][k];
            float a1 = sA[ty * 4 + 1][k];
            float a2 = sA[ty * 4 + 2][k];
            float a3 = sA[ty * 4 + 3][k];
            acc[0][0] += a0 * bv.x; acc[0][1] += a0 * bv.y; acc[0][2] += a0 * bv.z; acc[0][3] += a0 * bv.w;
            acc[1][0] += a1 * bv.x; acc[1][1] += a1 * bv.y; acc[1][2] += a1 * bv.z; acc[1][3] += a1 * bv.w;
            acc[2][0] += a2 * bv.x; acc[2][1] += a2 * bv.y; acc[2][2] += a2 * bv.z; acc[2][3] += a2 * bv.w;
            acc[3][0] += a3 * bv.x; acc[3][1] += a3 * bv.y; acc[3][2] += a3 * bv.z; acc[3][3] += a3 * bv.w;
        }
        __syncthreads();
    }

    float* xw = g_xw + ((size_t)dir * TT * BB + m0) * H3;
    #pragma unroll
    for (int i = 0; i < 4; i++) {
        int m = ty * 4 + i;
        int n = n0 + tx * 4;
        float4 o;
        o.x = acc[i][0] + bi[n + 0];
        o.y = acc[i][1] + bi[n + 1];
        o.z = acc[i][2] + bi[n + 2];
        o.w = acc[i][3] + bi[n + 3];
        *(float4*)&xw[(size_t)m * H3 + n] = o;
    }
}

// ---------------------------------------------------------------------------
// Persistent GRU scan kernel.
// Grid = 128 CTAs (1 per SM guaranteed by SMEM usage). CTA c: dir = c>>6,
// hidden-column block j0 = (c&63)*16. The CTA's slice of U (3 gates x 1024 k
// x 16 j = 192KB fp32) is staged into SMEM ONCE. Each timestep: stage h
// chunks (L1-bypassed), accumulate 3 gate dot-products per (b, j), apply
// gate nonlinearity, write new h + output, then software grid barrier.
// ---------------------------------------------------------------------------
#define SMEM_BYTES ((3 * 1024 * 16 + 64 * 68) * 4)

__global__ __launch_bounds__(256, 1) void gru_persistent(
    const float* __restrict__ Uf, const float* __restrict__ bf,
    const float* __restrict__ Ub, const float* __restrict__ bb,
    float* __restrict__ out)
{
    extern __shared__ float smem[];
    float* sU = smem;                    // [gate][k][16 j]
    float* sH = smem + 3 * 1024 * 16;    // [64 b][68]  (padded rows of k)

    const int cta  = blockIdx.x;         // 0..127
    const int dir  = cta >> 6;
    const int j0   = (cta & 63) * 16;

    const float* __restrict__ U    = dir ? Ub : Uf;
    const float* __restrict__ bias = dir ? bb : bf;

    const int tid = threadIdx.x;         // 256
    const int jl  = tid & 15;
    const int bq  = tid >> 4;            // 0..15
    const int j   = j0 + jl;
    const int b0  = bq * 4;

    // ---- Stage this CTA's U slice into SMEM (once) ----
    for (int i = tid; i < 3 * 1024 * 4; i += 256) {
        int g  = i >> 12;                // gate 0..2
        int k  = (i >> 2) & 1023;
        int c  = (i & 3) * 4;
        float4 v = *(const float4*)&U[(size_t)k * H3 + g * HH + j0 + c];
        *(float4*)&sU[((g << 10) + k) * 16 + c] = v;
    }
    const float brz = bias[H3 + j];
    const float brr = bias[H3 + HH + j];
    const float brh = bias[H3 + 2 * HH + j];
    __syncthreads();

    const int bld = tid >> 4;            // staging: batch row
    const int kld = (tid & 15) * 4;      // staging: k offset

    unsigned int bar_target = 0;

    for (int s = 0; s < TT; s++) {
        const int p  = s & 1;
        const int tt = dir ? (TT - 1 - s) : s;
        const float* __restrict__ hp = &g_h[dir][p][0][0];
        float* __restrict__ hn       = &g_h[dir][p ^ 1][0][0];
        const float* __restrict__ xw = g_xw + ((size_t)dir * TT + tt) * BB * H3;

        // Prefetch xw slice and h_prev for this thread's (4 b, 1 j)
        float xz[4], xr[4], xh[4], hprev[4];
        #pragma unroll
        for (int i = 0; i < 4; i++) {
            const float* xwb = xw + (size_t)(b0 + i) * H3;
            xz[i]    = xwb[j];
            xr[i]    = xwb[HH + j];
            xh[i]    = xwb[2 * HH + j];
            hprev[i] = __ldcv(&hp[(size_t)(b0 + i) * HH + j]);   // L1-bypass
        }

        float az[4] = {0.f, 0.f, 0.f, 0.f};
        float ar[4] = {0.f, 0.f, 0.f, 0.f};
        float ah[4] = {0.f, 0.f, 0.f, 0.f};

        for (int k0 = 0; k0 < HH; k0 += 64) {
            // Stage h chunk [64 b][64 k] into sH (natural [b][k] layout,
            // coalesced 256B-per-warp loads, L1 bypassed).
            const float* src = hp + k0 + kld;
            #pragma unroll
            for (int r = 0; r < 4; r++) {
                int b = bld + r * 16;
                float4 v = __ldcv((const float4*)(src + (size_t)b * HH));
                *(float4*)&sH[b * 68 + kld] = v;
            }
            __syncthreads();

            const float* uzp = &sU[(0 * 1024 + k0) * 16 + jl];
            const float* urp = &sU[(1 * 1024 + k0) * 16 + jl];
            const float* uhp = &sU[(2 * 1024 + k0) * 16 + jl];
            const float* h0p = &sH[(b0 + 0) * 68];
            const float* h1p = &sH[(b0 + 1) * 68];
            const float* h2p = &sH[(b0 + 2) * 68];
            const float* h3p = &sH[(b0 + 3) * 68];

            #pragma unroll 8
            for (int kk = 0; kk < 64; kk++) {
                float uz = uzp[kk * 16];
                float ur = urp[kk * 16];
                float uh = uhp[kk * 16];
                float h0 = h0p[kk];
                float h1 = h1p[kk];
                float h2 = h2p[kk];
                float h3 = h3p[kk];
                az[0] += h0 * uz; ar[0] += h0 * ur; ah[0] += h0 * uh;
                az[1] += h1 * uz; ar[1] += h1 * ur; ah[1] += h1 * uh;
                az[2] += h2 * uz; ar[2] += h2 * ur; ah[2] += h2 * uh;
                az[3] += h3 * uz; ar[3] += h3 * ur; ah[3] += h3 * uh;
            }
            __syncthreads();
        }

        // Gates + writes
        #pragma unroll
        for (int i = 0; i < 4; i++) {
            int b = b0 + i;
            float z    = 1.f / (1.f + __expf(-(xz[i] + az[i] + brz)));
            float r    = 1.f / (1.f + __expf(-(xr[i] + ar[i] + brr)));
            float cand = tanhf(xh[i] + r * (ah[i] + brh));
            float v    = z * hprev[i] + (1.f - z) * cand;
            hn[(size_t)b * HH + j] = v;
            out[((size_t)b * TT + tt) * (2 * HH) + dir * HH + j] = v;
            if (s == TT - 1)
                out[(size_t)BB * TT * 2 * HH + ((size_t)dir * BB + b) * HH + j] = v;
        }

        // ---- Grid barrier (per direction) ----
        __syncthreads();                     // all CTA threads done writing
        bar_target += 64;
        if (tid == 0) {
            __threadfence();                 // release h writes to L2
            atomicAdd(&g_bar[dir], 1u);
            while (*(volatile unsigned int*)&g_bar[dir] < bar_target) {
                __nanosleep(64);
            }
            __threadfence();                 // acquire
        }
        __syncthreads();
    }
}

// ---------------------------------------------------------------------------
// Launch. Inputs (metadata order): x, hidden, emb, Wf, Uf, bf, Wb, Ub, bb.
// Output: concat (B,T,2H) then hf (B,H) then hb (B,H), all float32.
// ---------------------------------------------------------------------------
extern "C" void kernel_launch(void* const* d_in, const int* in_sizes, int n_in,
                              void* d_out, int out_size)
{
    const int*   x      = (const int*)  d_in[0];
    const float* hidden = (const float*)d_in[1];
    const float* emb    = (const float*)d_in[2];
    const float* Wf     = (const float*)d_in[3];
    const float* Uf     = (const float*)d_in[4];
    const float* bf     = (const float*)d_in[5];
    const float* Wb     = (const float*)d_in[6];
    const float* Ub     = (const float*)d_in[7];
    const float* bb     = (const float*)d_in[8];
    float* out = (float*)d_out;

    cudaFuncSetAttribute(gru_persistent,
                         cudaFuncAttributeMaxDynamicSharedMemorySize, SMEM_BYTES);

    // Init hidden states + barrier counters
    init_h_kernel<<<(2 * BB * HH) / 256, 256>>>(hidden);

    // Input projections for both directions
    {
        dim3 grid(H3 / 64, (TT * BB) / 64, 2);
        input_proj_kernel<<<grid, 256>>>(x, emb, Wf, bf, Wb, bb);
    }

    // Persistent scan: one kernel, 256 internal steps with grid barriers
    gru_persistent<<<128, 256, SMEM_BYTES>>>(Uf, bf, Ub, bb, out);
}